// round 1
// baseline (speedup 1.0000x reference)
#include <cuda_runtime.h>
#include <math.h>

#define H 1024
#define M_ROWS 32768
#define BM 64
#define BN 64
#define BK 16

// Ping-pong hidden-state scratch (128 MiB each). Static __device__ globals:
// allocation-free per harness rules.
__device__ __align__(16) float g_bufA[(size_t)M_ROWS * H];
__device__ __align__(16) float g_bufB[(size_t)M_ROWS * H];

__device__ __forceinline__ float sigm(float x) { return 1.0f / (1.0f + expf(-x)); }

// Fused 3-matrix GEMM: computes acc_g[m][n] = sum_k A[m][k] * Bg[n][k] for g=0,1,2
// then applies either the GRU epilogue (MODE=0) or the highway epilogue (MODE=1).
//
// MODE 0 (initial GRU step, h0 = 0):
//   B0/B1/B2 = w_ih gate slices (r, z, n), e0 = b_ih, e1 = b_hh
//   r = sigmoid(acc0 + b_ih[n]      + b_hh[n])
//   z = sigmoid(acc1 + b_ih[H+n]    + b_hh[H+n])
//   nn= tanh   (acc2 + b_ih[2H+n]   + r * b_hh[2H+n])
//   out = (1 - z) * nn
//
// MODE 1 (micro step s):
//   B0=WH[s], B1=WT[s], B2=WC[s]; e0=bH[s], e1=bT[s], e2=bC[s]; hin = h
//   hh = tanh(acc0 + bH[n]); t = sigmoid(acc1 + bT[n]); c = sigmoid(acc2 + bC[n])
//   out = hh * t + hin * (1 - c)
template<int KTOT, int MODE>
__global__ void __launch_bounds__(256, 2)
rhn_fused3(const float* __restrict__ A,
           const float* __restrict__ B0,
           const float* __restrict__ B1,
           const float* __restrict__ B2,
           const float* __restrict__ e0,
           const float* __restrict__ e1,
           const float* __restrict__ e2,
           const float* __restrict__ hin,
           float* __restrict__ out)
{
    // k-major smem tiles, padded (+4) so transposed stores are conflict-free
    // and float4 reads stay 16B-aligned (row stride 68 floats = 272B = 17*16B).
    __shared__ __align__(16) float As[BK][BM + 4];
    __shared__ __align__(16) float Bs[3][BK][BN + 4];

    const int tid = threadIdx.x;
    const int tx = tid & 15;   // output column group (4 cols)
    const int ty = tid >> 4;   // output row group (4 rows)
    const int m0 = blockIdx.y * BM;
    const int n0 = blockIdx.x * BN;

    // Tile-load mapping: thread -> (row-in-tile, k-offset), one float4 per array.
    const int lr = tid >> 2;          // 0..63
    const int lk = (tid & 3) << 2;    // 0,4,8,12

    const float* aP  = A  + (size_t)(m0 + lr) * KTOT + lk;
    const float* b0P = B0 + (size_t)(n0 + lr) * KTOT + lk;
    const float* b1P = B1 + (size_t)(n0 + lr) * KTOT + lk;
    const float* b2P = B2 + (size_t)(n0 + lr) * KTOT + lk;

    float4 ra  = *(const float4*)aP;
    float4 rb0 = *(const float4*)b0P;
    float4 rb1 = *(const float4*)b1P;
    float4 rb2 = *(const float4*)b2P;

    float acc[3][4][4];
#pragma unroll
    for (int g = 0; g < 3; g++)
#pragma unroll
        for (int i = 0; i < 4; i++)
#pragma unroll
            for (int j = 0; j < 4; j++)
                acc[g][i][j] = 0.0f;

    const int NT = KTOT / BK;
    for (int kt = 0; kt < NT; kt++) {
        // commit prefetched tile to smem (transposed to k-major)
        As[lk + 0][lr] = ra.x;  As[lk + 1][lr] = ra.y;
        As[lk + 2][lr] = ra.z;  As[lk + 3][lr] = ra.w;
        Bs[0][lk + 0][lr] = rb0.x; Bs[0][lk + 1][lr] = rb0.y;
        Bs[0][lk + 2][lr] = rb0.z; Bs[0][lk + 3][lr] = rb0.w;
        Bs[1][lk + 0][lr] = rb1.x; Bs[1][lk + 1][lr] = rb1.y;
        Bs[1][lk + 2][lr] = rb1.z; Bs[1][lk + 3][lr] = rb1.w;
        Bs[2][lk + 0][lr] = rb2.x; Bs[2][lk + 1][lr] = rb2.y;
        Bs[2][lk + 2][lr] = rb2.z; Bs[2][lk + 3][lr] = rb2.w;
        __syncthreads();

        // prefetch next tile while computing on this one
        if (kt + 1 < NT) {
            aP += BK; b0P += BK; b1P += BK; b2P += BK;
            ra  = *(const float4*)aP;
            rb0 = *(const float4*)b0P;
            rb1 = *(const float4*)b1P;
            rb2 = *(const float4*)b2P;
        }

#pragma unroll
        for (int kk = 0; kk < BK; kk++) {
            float4 av  = *(const float4*)&As[kk][ty << 2];
            float4 bv0 = *(const float4*)&Bs[0][kk][tx << 2];
            float4 bv1 = *(const float4*)&Bs[1][kk][tx << 2];
            float4 bv2 = *(const float4*)&Bs[2][kk][tx << 2];
            float aa[4] = {av.x, av.y, av.z, av.w};
            float b0a[4] = {bv0.x, bv0.y, bv0.z, bv0.w};
            float b1a[4] = {bv1.x, bv1.y, bv1.z, bv1.w};
            float b2a[4] = {bv2.x, bv2.y, bv2.z, bv2.w};
#pragma unroll
            for (int i = 0; i < 4; i++) {
#pragma unroll
                for (int j = 0; j < 4; j++) {
                    acc[0][i][j] = fmaf(aa[i], b0a[j], acc[0][i][j]);
                    acc[1][i][j] = fmaf(aa[i], b1a[j], acc[1][i][j]);
                    acc[2][i][j] = fmaf(aa[i], b2a[j], acc[2][i][j]);
                }
            }
        }
        __syncthreads();
    }

    // ---- Epilogue ----
    const int nb = n0 + (tx << 2);

    if (MODE == 0) {
        float br[4], bz[4], bni[4], bnh[4];
#pragma unroll
        for (int j = 0; j < 4; j++) {
            int n = nb + j;
            br[j]  = e0[n]         + e1[n];
            bz[j]  = e0[H + n]     + e1[H + n];
            bni[j] = e0[2 * H + n];
            bnh[j] = e1[2 * H + n];
        }
#pragma unroll
        for (int i = 0; i < 4; i++) {
            int m = m0 + (ty << 2) + i;
            float4 o;
            float res[4];
#pragma unroll
            for (int j = 0; j < 4; j++) {
                float r  = sigm(acc[0][i][j] + br[j]);
                float z  = sigm(acc[1][i][j] + bz[j]);
                float nn = tanhf(acc[2][i][j] + bni[j] + r * bnh[j]);
                res[j] = (1.0f - z) * nn;
            }
            o.x = res[0]; o.y = res[1]; o.z = res[2]; o.w = res[3];
            *(float4*)&out[(size_t)m * H + nb] = o;
        }
    } else {
        float bh[4], bt[4], bc[4];
#pragma unroll
        for (int j = 0; j < 4; j++) {
            int n = nb + j;
            bh[j] = e0[n];
            bt[j] = e1[n];
            bc[j] = e2[n];
        }
#pragma unroll
        for (int i = 0; i < 4; i++) {
            int m = m0 + (ty << 2) + i;
            float4 hv = *(const float4*)&hin[(size_t)m * H + nb];
            float hva[4] = {hv.x, hv.y, hv.z, hv.w};
            float4 o;
            float res[4];
#pragma unroll
            for (int j = 0; j < 4; j++) {
                float hh = tanhf(acc[0][i][j] + bh[j]);
                float t  = sigm(acc[1][i][j] + bt[j]);
                float c  = sigm(acc[2][i][j] + bc[j]);
                res[j] = hh * t + hva[j] * (1.0f - c);
            }
            o.x = res[0]; o.y = res[1]; o.z = res[2]; o.w = res[3];
            *(float4*)&out[(size_t)m * H + nb] = o;
        }
    }
}

extern "C" void kernel_launch(void* const* d_in, const int* in_sizes, int n_in,
                              void* d_out, int out_size)
{
    const float* x    = (const float*)d_in[0];
    const float* w_ih = (const float*)d_in[1];
    // d_in[2] = w_hh: mathematically unused (h0 = 0)
    const float* b_ih = (const float*)d_in[3];
    const float* b_hh = (const float*)d_in[4];
    const float* WH   = (const float*)d_in[5];
    const float* bH   = (const float*)d_in[6];
    const float* WT   = (const float*)d_in[7];
    const float* bT   = (const float*)d_in[8];
    const float* WC   = (const float*)d_in[9];
    const float* bC   = (const float*)d_in[10];
    float* out = (float*)d_out;

    float *bufA, *bufB;
    cudaGetSymbolAddress((void**)&bufA, g_bufA);
    cudaGetSymbolAddress((void**)&bufB, g_bufB);

    dim3 blk(256);
    dim3 grd(H / BN, M_ROWS / BM);

    // Initial GRU gate GEMM (K = 512): x -> h  into bufA
    rhn_fused3<512, 0><<<grd, blk>>>(
        x,
        w_ih,
        w_ih + (size_t)H * 512,
        w_ih + (size_t)2 * H * 512,
        b_ih, b_hh, nullptr, nullptr,
        bufA);

    // 5 highway micro-steps (K = 1024), ping-pong; last writes d_out.
    for (int s = 0; s < 5; s++) {
        const float* hi = (s & 1) ? bufB : bufA;
        float* ho = (s == 4) ? out : ((s & 1) ? bufA : bufB);
        rhn_fused3<1024, 1><<<grd, blk>>>(
            hi,
            WH + (size_t)s * H * H,
            WT + (size_t)s * H * H,
            WC + (size_t)s * H * H,
            bH + s * H, bT + s * H, bC + s * H,
            hi,
            ho);
    }
}